// round 2
// baseline (speedup 1.0000x reference)
#include <cuda_runtime.h>
#include <math.h>

// Problem constants
#define B_ 2
#define T_ 2048
#define D_ 1024
#define H_ 16
#define DH_ 64
#define NROW (B_ * T_)        // 4096
#define BH_ (B_ * H_)         // 32

// ---------------------------------------------------------------------------
// Scratch (static device allocations are allowed)
// ---------------------------------------------------------------------------
__device__ float g_qkv[(size_t)NROW * 3 * D_];          // [4096, 3072]
__device__ float g_q[(size_t)BH_ * T_ * DH_];           // [32, 2048, 64]
__device__ float g_k[(size_t)BH_ * T_ * DH_];
__device__ float g_v[(size_t)BH_ * T_ * DH_];
__device__ float g_attn[(size_t)NROW * D_];             // [4096, 1024]

// ---------------------------------------------------------------------------
// SGEMM: C[M,N] = A[M,K] @ B[K,N] (+ bias). 128x128 block, BK=8, 8x8/thread.
// Requires M%128==0, N%128==0, K%8==0 (true for all our shapes).
// ---------------------------------------------------------------------------
__global__ void __launch_bounds__(256, 2)
sgemm128(const float* __restrict__ A, const float* __restrict__ B,
         const float* __restrict__ bias, float* __restrict__ C,
         int M, int N, int K)
{
    __shared__ float As[8][128];
    __shared__ float Bs[8][128];

    const int bm = blockIdx.y * 128;
    const int bn = blockIdx.x * 128;
    const int tid = threadIdx.x;
    const int tx = tid & 15;        // 0..15  -> 8 output cols
    const int ty = tid >> 4;        // 0..15  -> 8 output rows

    const int arow = tid >> 1;             // 0..127
    const int acol = (tid & 1) * 4;        // 0 or 4
    const int brow = tid >> 5;             // 0..7
    const int bcol = (tid & 31) * 4;       // 0..124

    const float* Aptr = A + (size_t)(bm + arow) * K + acol;
    const float* Bptr = B + (size_t)brow * N + bn + bcol;

    float acc[8][8];
#pragma unroll
    for (int i = 0; i < 8; i++)
#pragma unroll
        for (int j = 0; j < 8; j++) acc[i][j] = 0.0f;

    for (int kt = 0; kt < K; kt += 8) {
        float4 a4 = *(const float4*)(Aptr + kt);
        float4 b4 = *(const float4*)(Bptr + (size_t)kt * N);
        As[acol + 0][arow] = a4.x;
        As[acol + 1][arow] = a4.y;
        As[acol + 2][arow] = a4.z;
        As[acol + 3][arow] = a4.w;
        *(float4*)&Bs[brow][bcol] = b4;
        __syncthreads();

#pragma unroll
        for (int k = 0; k < 8; k++) {
            float4 a0 = *(const float4*)&As[k][ty * 8];
            float4 a1 = *(const float4*)&As[k][ty * 8 + 4];
            float4 b0 = *(const float4*)&Bs[k][tx * 8];
            float4 b1 = *(const float4*)&Bs[k][tx * 8 + 4];
            float af[8] = {a0.x, a0.y, a0.z, a0.w, a1.x, a1.y, a1.z, a1.w};
            float bf[8] = {b0.x, b0.y, b0.z, b0.w, b1.x, b1.y, b1.z, b1.w};
#pragma unroll
            for (int i = 0; i < 8; i++)
#pragma unroll
                for (int j = 0; j < 8; j++)
                    acc[i][j] += af[i] * bf[j];
        }
        __syncthreads();
    }

#pragma unroll
    for (int i = 0; i < 8; i++) {
        const int row = bm + ty * 8 + i;
#pragma unroll
        for (int j4 = 0; j4 < 2; j4++) {
            const int col = bn + tx * 8 + j4 * 4;
            float4 v;
            if (bias) {
                v.x = acc[i][j4 * 4 + 0] + bias[col + 0];
                v.y = acc[i][j4 * 4 + 1] + bias[col + 1];
                v.z = acc[i][j4 * 4 + 2] + bias[col + 2];
                v.w = acc[i][j4 * 4 + 3] + bias[col + 3];
            } else {
                v.x = acc[i][j4 * 4 + 0];
                v.y = acc[i][j4 * 4 + 1];
                v.z = acc[i][j4 * 4 + 2];
                v.w = acc[i][j4 * 4 + 3];
            }
            *(float4*)&C[(size_t)row * N + col] = v;
        }
    }
}

// ---------------------------------------------------------------------------
// RoPE + split + transpose: g_qkv[b,t,(s,h,d)] -> g_q/g_k/g_v [bh, t, d]
// q is pre-scaled by 1/sqrt(DH) = 0.125.
// One thread per (b,h,t,d2) with d2 in [0,32): handles the (d2, d2+32) pair.
// ---------------------------------------------------------------------------
__global__ void rope_split_kernel()
{
    const int idx = blockIdx.x * blockDim.x + threadIdx.x;
    const int d2 = idx & 31;
    const int t  = (idx >> 5) & (T_ - 1);
    const int bh = idx >> 16;           // /(32*2048)
    const int h = bh & (H_ - 1);
    const int b = bh >> 4;

    const float* row = g_qkv + ((size_t)(b * T_ + t)) * (3 * D_) + h * DH_;
    const float q0 = row[d2];
    const float q1 = row[d2 + 32];
    const float k0 = row[D_ + d2];
    const float k1 = row[D_ + d2 + 32];
    const float v0 = row[2 * D_ + d2];
    const float v1 = row[2 * D_ + d2 + 32];

    const float inv = 1.0f / powf(10000.0f, (float)d2 * (1.0f / 32.0f));
    const float ang = (float)t * inv;
    float sn, cs;
    sincosf(ang, &sn, &cs);

    const size_t obase = ((size_t)bh * T_ + t) * DH_;
    g_q[obase + d2]      = (q0 * cs - q1 * sn) * 0.125f;
    g_q[obase + d2 + 32] = (q1 * cs + q0 * sn) * 0.125f;
    g_k[obase + d2]      = k0 * cs - k1 * sn;
    g_k[obase + d2 + 32] = k1 * cs + k0 * sn;
    g_v[obase + d2]      = v0;
    g_v[obase + d2 + 32] = v1;
}

// ---------------------------------------------------------------------------
// Flash-style causal attention. One block per (q-tile of 64 rows, bh).
// 8 warps; warp w owns q rows w*8..w*8+7; lane owns keys {lane, lane+32} and
// output dims {lane, lane+32}. Online softmax, fp32 throughout.
// Dynamic smem: qs[64][64], ks[64][65], vs[64][64], ps[64][64].
// ---------------------------------------------------------------------------
#define ATTN_SMEM ((64 * 64 + 64 * 65 + 64 * 64 + 64 * 64) * 4)

__global__ void __launch_bounds__(256)
attn_kernel()
{
    extern __shared__ float sm[];
    float* qs = sm;                         // [64][64]
    float* ks = sm + 64 * 64;               // [64][65] (pad for column reads)
    float* vs = ks + 64 * 65;               // [64][64]
    float* ps = vs + 64 * 64;               // [64][64] (warp-private rows)

    const int qt = blockIdx.x;              // 0..31
    const int bh = blockIdx.y;              // 0..31
    const int tid = threadIdx.x;
    const int lane = tid & 31;
    const int w = tid >> 5;

    const float* Qb = g_q + ((size_t)bh * T_ + qt * 64) * DH_;
    const float* Kb = g_k + (size_t)bh * T_ * DH_;
    const float* Vb = g_v + (size_t)bh * T_ * DH_;

    // load q tile: 64x64 floats = 1024 float4s, 256 threads x 4 iterations
#pragma unroll
    for (int i = 0; i < 4; i++) {
        const int e = tid + i * 256;        // 0..1023
        const int r = e >> 4;               // 0..63
        const int c = (e & 15) << 2;        // 0..60
        *(float4*)&qs[r * 64 + c] = *(const float4*)&Qb[r * 64 + c];
    }

    float m[8], l[8], o0[8], o1[8];
#pragma unroll
    for (int i = 0; i < 8; i++) { m[i] = -1e30f; l[i] = 0.f; o0[i] = 0.f; o1[i] = 0.f; }

    for (int kt = 0; kt <= qt; kt++) {
        __syncthreads();   // previous-iteration readers of ks/vs done; qs store visible on iter 0
#pragma unroll
        for (int i = 0; i < 4; i++) {
            const int e = tid + i * 256;
            const int r = e >> 4;           // 0..63
            const int c = (e & 15) << 2;    // 0..60
            float4 k4 = *(const float4*)(Kb + (size_t)(kt * 64 + r) * 64 + c);
            ks[r * 65 + c + 0] = k4.x;
            ks[r * 65 + c + 1] = k4.y;
            ks[r * 65 + c + 2] = k4.z;
            ks[r * 65 + c + 3] = k4.w;
            float4 v4 = *(const float4*)(Vb + (size_t)(kt * 64 + r) * 64 + c);
            *(float4*)&vs[r * 64 + c] = v4;
        }
        __syncthreads();

        // --- scores: lane computes s for keys (lane) and (lane+32) ---
        float s0[8], s1[8];
#pragma unroll
        for (int i = 0; i < 8; i++) { s0[i] = 0.f; s1[i] = 0.f; }

#pragma unroll 4
        for (int d = 0; d < 64; d += 4) {
            const float ka0 = ks[lane * 65 + d + 0];
            const float ka1 = ks[lane * 65 + d + 1];
            const float ka2 = ks[lane * 65 + d + 2];
            const float ka3 = ks[lane * 65 + d + 3];
            const float kb0 = ks[(lane + 32) * 65 + d + 0];
            const float kb1 = ks[(lane + 32) * 65 + d + 1];
            const float kb2 = ks[(lane + 32) * 65 + d + 2];
            const float kb3 = ks[(lane + 32) * 65 + d + 3];
#pragma unroll
            for (int i = 0; i < 8; i++) {
                float4 q4 = *(const float4*)&qs[(w * 8 + i) * 64 + d];
                s0[i] += q4.x * ka0 + q4.y * ka1 + q4.z * ka2 + q4.w * ka3;
                s1[i] += q4.x * kb0 + q4.y * kb1 + q4.z * kb2 + q4.w * kb3;
            }
        }

        // --- online softmax + stage p into warp-private shared rows ---
        const bool diag = (kt == qt);
#pragma unroll
        for (int i = 0; i < 8; i++) {
            const int r = w * 8 + i;
            if (diag) {
                if (lane > r)      s0[i] = -1e30f;
                if (lane + 32 > r) s1[i] = -1e30f;
            }
            float tmax = fmaxf(s0[i], s1[i]);
#pragma unroll
            for (int off = 16; off; off >>= 1)
                tmax = fmaxf(tmax, __shfl_xor_sync(0xffffffffu, tmax, off));
            const float mnew = fmaxf(m[i], tmax);
            const float corr = __expf(m[i] - mnew);
            const float p0 = __expf(s0[i] - mnew);
            const float p1 = __expf(s1[i] - mnew);
            float tsum = p0 + p1;
#pragma unroll
            for (int off = 16; off; off >>= 1)
                tsum += __shfl_xor_sync(0xffffffffu, tsum, off);
            l[i] = l[i] * corr + tsum;
            o0[i] *= corr;
            o1[i] *= corr;
            m[i] = mnew;
            ps[r * 64 + lane]      = p0;
            ps[r * 64 + lane + 32] = p1;
        }
        __syncwarp();

        // --- o += P @ V : lane accumulates dims (lane) and (lane+32) ---
#pragma unroll 4
        for (int j = 0; j < 64; j += 4) {
            float va[4], vb[4];
#pragma unroll
            for (int jj = 0; jj < 4; jj++) {
                va[jj] = vs[(j + jj) * 64 + lane];
                vb[jj] = vs[(j + jj) * 64 + lane + 32];
            }
#pragma unroll
            for (int i = 0; i < 8; i++) {
                float4 p4 = *(const float4*)&ps[(w * 8 + i) * 64 + j];
                o0[i] += p4.x * va[0] + p4.y * va[1] + p4.z * va[2] + p4.w * va[3];
                o1[i] += p4.x * vb[0] + p4.y * vb[1] + p4.z * vb[2] + p4.w * vb[3];
            }
        }
    }

    // epilogue: normalize + write to g_attn[b, t, h*64 + d]
    const int b = bh >> 4;
    const int h = bh & (H_ - 1);
#pragma unroll
    for (int i = 0; i < 8; i++) {
        const float inv_l = 1.0f / l[i];
        const int t = qt * 64 + w * 8 + i;
        const size_t base = ((size_t)(b * T_ + t)) * D_ + h * DH_;
        g_attn[base + lane]      = o0[i] * inv_l;
        g_attn[base + lane + 32] = o1[i] * inv_l;
    }
}

// ---------------------------------------------------------------------------
// kernel_launch
// inputs: 0=x [B,T,D] f32, 1=mask (ignored, causal known), 2=qkv_w [D,3D],
//         3=out_w [D,D], 4=out_b [D]. output: [B,T,D] f32.
// ---------------------------------------------------------------------------
extern "C" void kernel_launch(void* const* d_in, const int* in_sizes, int n_in,
                              void* d_out, int out_size)
{
    (void)in_sizes; (void)n_in; (void)out_size;
    const float* x     = (const float*)d_in[0];
    const float* qkv_w = (const float*)d_in[2];
    const float* out_w = (const float*)d_in[3];
    const float* out_b = (const float*)d_in[4];
    float* out = (float*)d_out;

    void* p_qkv;
    void* p_attn;
    cudaGetSymbolAddress(&p_qkv, g_qkv);
    cudaGetSymbolAddress(&p_attn, g_attn);

    cudaFuncSetAttribute(attn_kernel,
                         cudaFuncAttributeMaxDynamicSharedMemorySize, ATTN_SMEM);

    // 1) QKV projection
    sgemm128<<<dim3((3 * D_) / 128, NROW / 128), 256>>>(
        x, qkv_w, nullptr, (float*)p_qkv, NROW, 3 * D_, D_);

    // 2) RoPE + split/transpose
    rope_split_kernel<<<(BH_ * T_ * 32) / 256, 256>>>();

    // 3) causal flash attention
    attn_kernel<<<dim3(T_ / 64, BH_), 256, ATTN_SMEM>>>();

    // 4) output projection + bias
    sgemm128<<<dim3(D_ / 128, NROW / 128), 256>>>(
        (const float*)p_attn, out_w, out_b, out, NROW, D_, D_);
}

// round 3
// speedup vs baseline: 1.2915x; 1.2915x over previous
#include <cuda_runtime.h>
#include <math.h>

// Problem constants
#define B_ 2
#define T_ 2048
#define D_ 1024
#define H_ 16
#define DH_ 64
#define NROW (B_ * T_)        // 4096
#define BH_ (B_ * H_)         // 32

// ---------------------------------------------------------------------------
// Scratch
// ---------------------------------------------------------------------------
__device__ float g_qkv[(size_t)NROW * 3 * D_];          // [4096, 3072]
__device__ float g_q[(size_t)BH_ * T_ * DH_];           // [32, 2048, 64]
__device__ float g_k[(size_t)BH_ * T_ * DH_];
__device__ float g_v[(size_t)BH_ * T_ * DH_];
__device__ float g_attn[(size_t)NROW * D_];             // [4096, 1024]

// ---------------------------------------------------------------------------
// tf32 helpers
// ---------------------------------------------------------------------------
__device__ __forceinline__ unsigned f2tf32(float x) {
    unsigned r;
    asm("cvt.rna.tf32.f32 %0, %1;" : "=r"(r) : "f"(x));
    return r;
}

__device__ __forceinline__ void mma_tf32(float& c0, float& c1, float& c2, float& c3,
                                         unsigned a0, unsigned a1, unsigned a2, unsigned a3,
                                         unsigned b0, unsigned b1) {
    asm volatile("mma.sync.aligned.m16n8k8.row.col.f32.tf32.tf32.f32 "
                 "{%0,%1,%2,%3}, {%4,%5,%6,%7}, {%8,%9}, {%0,%1,%2,%3};"
                 : "+f"(c0), "+f"(c1), "+f"(c2), "+f"(c3)
                 : "r"(a0), "r"(a1), "r"(a2), "r"(a3), "r"(b0), "r"(b1));
}

// ---------------------------------------------------------------------------
// tf32 tensor-core GEMM: C[M,N] = A[M,K] @ B[K,N] (+bias)
// Block 128x128, BK=32, 128 threads = 4 warps, warp tile 64x64.
// Requires M%128==0, N%128==0, K%32==0.
// A staged K-major transposed (Ast[k][m]), B row-major (Bs[k][n]); both tf32.
// ---------------------------------------------------------------------------
#define GPAD 4
__global__ void __launch_bounds__(128)
gemm_tf32(const float* __restrict__ A, const float* __restrict__ B,
          const float* __restrict__ bias, float* __restrict__ C,
          int M, int N, int K)
{
    __shared__ unsigned Ast[32][128 + GPAD];
    __shared__ unsigned Bs[32][128 + GPAD];

    const int bm = blockIdx.y * 128;
    const int bn = blockIdx.x * 128;
    const int tid = threadIdx.x;
    const int lane = tid & 31;
    const int w = tid >> 5;
    const int wm = (w & 1) * 64;    // warp m offset in block
    const int wn = (w >> 1) * 64;   // warp n offset in block

    // global load mappings
    // A: thread t owns row (bm + t), loads 8 float4 across the 32-wide k slice
    const float* Arow = A + (size_t)(bm + tid) * K;
    // B: thread t owns k-row (t>>2), n-range (t&3)*32 .. +31
    const int bk_row = tid >> 2;
    const int bn0 = (tid & 3) * 32;
    const float* Brow0 = B + bn + bn0;

    float acc[4][8][4];
#pragma unroll
    for (int mt = 0; mt < 4; mt++)
#pragma unroll
        for (int nt = 0; nt < 8; nt++)
#pragma unroll
            for (int i = 0; i < 4; i++) acc[mt][nt][i] = 0.0f;

    const int lrow = lane >> 2;    // 0..7
    const int lk = lane & 3;       // 0..3

    for (int kt = 0; kt < K; kt += 32) {
        // ---- stage A (transposed) ----
#pragma unroll
        for (int i = 0; i < 8; i++) {
            float4 a4 = *(const float4*)(Arow + kt + i * 4);
            Ast[i * 4 + 0][tid] = f2tf32(a4.x);
            Ast[i * 4 + 1][tid] = f2tf32(a4.y);
            Ast[i * 4 + 2][tid] = f2tf32(a4.z);
            Ast[i * 4 + 3][tid] = f2tf32(a4.w);
        }
        // ---- stage B ----
        const float* bp = Brow0 + (size_t)(kt + bk_row) * N;
#pragma unroll
        for (int i = 0; i < 8; i++) {
            float4 b4 = *(const float4*)(bp + i * 4);
            uint4 u;
            u.x = f2tf32(b4.x); u.y = f2tf32(b4.y);
            u.z = f2tf32(b4.z); u.w = f2tf32(b4.w);
            *(uint4*)&Bs[bk_row][bn0 + i * 4] = u;
        }
        __syncthreads();

        // ---- compute 4 ksteps ----
#pragma unroll
        for (int ks = 0; ks < 4; ks++) {
            const int k0 = ks * 8 + lk;
            unsigned afr[4][4];
#pragma unroll
            for (int mt = 0; mt < 4; mt++) {
                const int row = wm + mt * 16 + lrow;
                afr[mt][0] = Ast[k0][row];
                afr[mt][1] = Ast[k0][row + 8];
                afr[mt][2] = Ast[k0 + 4][row];
                afr[mt][3] = Ast[k0 + 4][row + 8];
            }
#pragma unroll
            for (int nt = 0; nt < 8; nt++) {
                const int n0 = wn + nt * 8 + lrow;
                unsigned b0 = Bs[k0][n0];
                unsigned b1 = Bs[k0 + 4][n0];
#pragma unroll
                for (int mt = 0; mt < 4; mt++)
                    mma_tf32(acc[mt][nt][0], acc[mt][nt][1], acc[mt][nt][2], acc[mt][nt][3],
                             afr[mt][0], afr[mt][1], afr[mt][2], afr[mt][3], b0, b1);
            }
        }
        __syncthreads();
    }

    // ---- epilogue ----
#pragma unroll
    for (int mt = 0; mt < 4; mt++) {
        const int row0 = bm + wm + mt * 16 + lrow;
#pragma unroll
        for (int nt = 0; nt < 8; nt++) {
            const int col = bn + wn + nt * 8 + lk * 2;
            float bx = 0.f, by = 0.f;
            if (bias) { bx = bias[col]; by = bias[col + 1]; }
            float2 v0 = make_float2(acc[mt][nt][0] + bx, acc[mt][nt][1] + by);
            float2 v1 = make_float2(acc[mt][nt][2] + bx, acc[mt][nt][3] + by);
            *(float2*)&C[(size_t)row0 * N + col] = v0;
            *(float2*)&C[(size_t)(row0 + 8) * N + col] = v1;
        }
    }
}

// ---------------------------------------------------------------------------
// RoPE + split + transpose: g_qkv[b,t,(s,h,d)] -> g_q/g_k/g_v [bh, t, d]
// q is pre-scaled by 1/sqrt(DH) = 0.125.
// ---------------------------------------------------------------------------
__global__ void rope_split_kernel()
{
    const int idx = blockIdx.x * blockDim.x + threadIdx.x;
    const int d2 = idx & 31;
    const int t  = (idx >> 5) & (T_ - 1);
    const int bh = idx >> 16;
    const int h = bh & (H_ - 1);
    const int b = bh >> 4;

    const float* row = g_qkv + ((size_t)(b * T_ + t)) * (3 * D_) + h * DH_;
    const float q0 = row[d2];
    const float q1 = row[d2 + 32];
    const float k0 = row[D_ + d2];
    const float k1 = row[D_ + d2 + 32];
    const float v0 = row[2 * D_ + d2];
    const float v1 = row[2 * D_ + d2 + 32];

    const float inv = 1.0f / powf(10000.0f, (float)d2 * (1.0f / 32.0f));
    const float ang = (float)t * inv;
    float sn, cs;
    sincosf(ang, &sn, &cs);

    const size_t obase = ((size_t)bh * T_ + t) * DH_;
    g_q[obase + d2]      = (q0 * cs - q1 * sn) * 0.125f;
    g_q[obase + d2 + 32] = (q1 * cs + q0 * sn) * 0.125f;
    g_k[obase + d2]      = k0 * cs - k1 * sn;
    g_k[obase + d2 + 32] = k1 * cs + k0 * sn;
    g_v[obase + d2]      = v0;
    g_v[obase + d2 + 32] = v1;
}

// ---------------------------------------------------------------------------
// Flash-style causal attention (fp32). One block per (64-row q tile, bh).
// ---------------------------------------------------------------------------
#define ATTN_SMEM ((64 * 64 + 64 * 65 + 64 * 64 + 64 * 64) * 4)

__global__ void __launch_bounds__(256)
attn_kernel()
{
    extern __shared__ float sm[];
    float* qs = sm;                         // [64][64]
    float* ks = sm + 64 * 64;               // [64][65]
    float* vs = ks + 64 * 65;               // [64][64]
    float* ps = vs + 64 * 64;               // [64][64]

    const int qt = blockIdx.x;
    const int bh = blockIdx.y;
    const int tid = threadIdx.x;
    const int lane = tid & 31;
    const int w = tid >> 5;

    const float* Qb = g_q + ((size_t)bh * T_ + qt * 64) * DH_;
    const float* Kb = g_k + (size_t)bh * T_ * DH_;
    const float* Vb = g_v + (size_t)bh * T_ * DH_;

#pragma unroll
    for (int i = 0; i < 4; i++) {
        const int e = tid + i * 256;
        const int r = e >> 4;
        const int c = (e & 15) << 2;
        *(float4*)&qs[r * 64 + c] = *(const float4*)&Qb[r * 64 + c];
    }

    float m[8], l[8], o0[8], o1[8];
#pragma unroll
    for (int i = 0; i < 8; i++) { m[i] = -1e30f; l[i] = 0.f; o0[i] = 0.f; o1[i] = 0.f; }

    for (int kt = 0; kt <= qt; kt++) {
        __syncthreads();
#pragma unroll
        for (int i = 0; i < 4; i++) {
            const int e = tid + i * 256;
            const int r = e >> 4;
            const int c = (e & 15) << 2;
            float4 k4 = *(const float4*)(Kb + (size_t)(kt * 64 + r) * 64 + c);
            ks[r * 65 + c + 0] = k4.x;
            ks[r * 65 + c + 1] = k4.y;
            ks[r * 65 + c + 2] = k4.z;
            ks[r * 65 + c + 3] = k4.w;
            float4 v4 = *(const float4*)(Vb + (size_t)(kt * 64 + r) * 64 + c);
            *(float4*)&vs[r * 64 + c] = v4;
        }
        __syncthreads();

        float s0[8], s1[8];
#pragma unroll
        for (int i = 0; i < 8; i++) { s0[i] = 0.f; s1[i] = 0.f; }

#pragma unroll 4
        for (int d = 0; d < 64; d += 4) {
            const float ka0 = ks[lane * 65 + d + 0];
            const float ka1 = ks[lane * 65 + d + 1];
            const float ka2 = ks[lane * 65 + d + 2];
            const float ka3 = ks[lane * 65 + d + 3];
            const float kb0 = ks[(lane + 32) * 65 + d + 0];
            const float kb1 = ks[(lane + 32) * 65 + d + 1];
            const float kb2 = ks[(lane + 32) * 65 + d + 2];
            const float kb3 = ks[(lane + 32) * 65 + d + 3];
#pragma unroll
            for (int i = 0; i < 8; i++) {
                float4 q4 = *(const float4*)&qs[(w * 8 + i) * 64 + d];
                s0[i] += q4.x * ka0 + q4.y * ka1 + q4.z * ka2 + q4.w * ka3;
                s1[i] += q4.x * kb0 + q4.y * kb1 + q4.z * kb2 + q4.w * kb3;
            }
        }

        const bool diag = (kt == qt);
#pragma unroll
        for (int i = 0; i < 8; i++) {
            const int r = w * 8 + i;
            if (diag) {
                if (lane > r)      s0[i] = -1e30f;
                if (lane + 32 > r) s1[i] = -1e30f;
            }
            float tmax = fmaxf(s0[i], s1[i]);
#pragma unroll
            for (int off = 16; off; off >>= 1)
                tmax = fmaxf(tmax, __shfl_xor_sync(0xffffffffu, tmax, off));
            const float mnew = fmaxf(m[i], tmax);
            const float corr = __expf(m[i] - mnew);
            const float p0 = __expf(s0[i] - mnew);
            const float p1 = __expf(s1[i] - mnew);
            float tsum = p0 + p1;
#pragma unroll
            for (int off = 16; off; off >>= 1)
                tsum += __shfl_xor_sync(0xffffffffu, tsum, off);
            l[i] = l[i] * corr + tsum;
            o0[i] *= corr;
            o1[i] *= corr;
            m[i] = mnew;
            ps[r * 64 + lane]      = p0;
            ps[r * 64 + lane + 32] = p1;
        }
        __syncwarp();

#pragma unroll 4
        for (int j = 0; j < 64; j += 4) {
            float va[4], vb[4];
#pragma unroll
            for (int jj = 0; jj < 4; jj++) {
                va[jj] = vs[(j + jj) * 64 + lane];
                vb[jj] = vs[(j + jj) * 64 + lane + 32];
            }
#pragma unroll
            for (int i = 0; i < 8; i++) {
                float4 p4 = *(const float4*)&ps[(w * 8 + i) * 64 + j];
                o0[i] += p4.x * va[0] + p4.y * va[1] + p4.z * va[2] + p4.w * va[3];
                o1[i] += p4.x * vb[0] + p4.y * vb[1] + p4.z * vb[2] + p4.w * vb[3];
            }
        }
    }

    const int b = bh >> 4;
    const int h = bh & (H_ - 1);
#pragma unroll
    for (int i = 0; i < 8; i++) {
        const float inv_l = 1.0f / l[i];
        const int t = qt * 64 + w * 8 + i;
        const size_t base = ((size_t)(b * T_ + t)) * D_ + h * DH_;
        g_attn[base + lane]      = o0[i] * inv_l;
        g_attn[base + lane + 32] = o1[i] * inv_l;
    }
}

// ---------------------------------------------------------------------------
// kernel_launch
// ---------------------------------------------------------------------------
extern "C" void kernel_launch(void* const* d_in, const int* in_sizes, int n_in,
                              void* d_out, int out_size)
{
    (void)in_sizes; (void)n_in; (void)out_size;
    const float* x     = (const float*)d_in[0];
    const float* qkv_w = (const float*)d_in[2];
    const float* out_w = (const float*)d_in[3];
    const float* out_b = (const float*)d_in[4];
    float* out = (float*)d_out;

    void* p_qkv;
    void* p_attn;
    cudaGetSymbolAddress(&p_qkv, g_qkv);
    cudaGetSymbolAddress(&p_attn, g_attn);

    cudaFuncSetAttribute(attn_kernel,
                         cudaFuncAttributeMaxDynamicSharedMemorySize, ATTN_SMEM);

    // 1) QKV projection (tf32 tensor cores)
    gemm_tf32<<<dim3((3 * D_) / 128, NROW / 128), 128>>>(
        x, qkv_w, nullptr, (float*)p_qkv, NROW, 3 * D_, D_);

    // 2) RoPE + split/transpose
    rope_split_kernel<<<(BH_ * T_ * 32) / 256, 256>>>();

    // 3) causal flash attention
    attn_kernel<<<dim3(T_ / 64, BH_), 256, ATTN_SMEM>>>();

    // 4) output projection + bias (tf32 tensor cores)
    gemm_tf32<<<dim3(D_ / 128, NROW / 128), 128>>>(
        (const float*)p_attn, out_w, out_b, out, NROW, D_, D_);
}

// round 4
// speedup vs baseline: 2.6862x; 2.0798x over previous
#include <cuda_runtime.h>
#include <math.h>

// Problem constants
#define B_ 2
#define T_ 2048
#define D_ 1024
#define H_ 16
#define DH_ 64
#define NROW (B_ * T_)        // 4096
#define BH_ (B_ * H_)         // 32

// ---------------------------------------------------------------------------
// Scratch
// ---------------------------------------------------------------------------
__device__ float g_qkv[(size_t)NROW * 3 * D_];          // [4096, 3072]
__device__ float g_q[(size_t)BH_ * T_ * DH_];           // [32, 2048, 64]
__device__ float g_k[(size_t)BH_ * T_ * DH_];
__device__ float g_v[(size_t)BH_ * T_ * DH_];
__device__ float g_attn[(size_t)NROW * D_];             // [4096, 1024]

// ---------------------------------------------------------------------------
// tf32 helpers
// ---------------------------------------------------------------------------
__device__ __forceinline__ unsigned f2tf32(float x) {
    unsigned r;
    asm("cvt.rna.tf32.f32 %0, %1;" : "=r"(r) : "f"(x));
    return r;
}

__device__ __forceinline__ void mma_tf32(float* c,
                                         unsigned a0, unsigned a1, unsigned a2, unsigned a3,
                                         unsigned b0, unsigned b1) {
    asm volatile("mma.sync.aligned.m16n8k8.row.col.f32.tf32.tf32.f32 "
                 "{%0,%1,%2,%3}, {%4,%5,%6,%7}, {%8,%9}, {%0,%1,%2,%3};"
                 : "+f"(c[0]), "+f"(c[1]), "+f"(c[2]), "+f"(c[3])
                 : "r"(a0), "r"(a1), "r"(a2), "r"(a3), "r"(b0), "r"(b1));
}

// ---------------------------------------------------------------------------
// tf32 GEMM: C[M,N] = A[M,K] @ B[K,N] (+bias)
// Block 128x128, BK=32, 256 threads = 8 warps (2m x 4n), warp tile 64x32.
// A staged row-major As[128][36], B row-major Bs[32][136]; global prefetch
// overlapped with compute. Requires M%128==0, N%128==0, K%32==0.
// ---------------------------------------------------------------------------
__global__ void __launch_bounds__(256, 2)
gemm_tf32(const float* __restrict__ A, const float* __restrict__ B,
          const float* __restrict__ bias, float* __restrict__ C,
          int M, int N, int K)
{
    __shared__ unsigned As[128][36];
    __shared__ unsigned Bs[32][136];

    const int bm = blockIdx.y * 128;
    const int bn = blockIdx.x * 128;
    const int tid = threadIdx.x;
    const int lane = tid & 31;
    const int w = tid >> 5;
    const int lrow = lane >> 2;
    const int lk = lane & 3;
    const int wm = (w & 1) * 64;
    const int wn = (w >> 1) * 32;

    // staging mappings
    const int arow = tid >> 1;              // 0..127
    const int abase = (tid & 1) * 16;       // 0 or 16
    const int brow = tid >> 3;              // 0..31
    const int bcol = (tid & 7) * 16;        // 0..112

    const float* Aptr = A + (size_t)(bm + arow) * K + abase;
    const float* Bptr = B + (size_t)brow * N + bn + bcol;

    float acc[4][4][4];
#pragma unroll
    for (int mt = 0; mt < 4; mt++)
#pragma unroll
        for (int nt = 0; nt < 4; nt++)
#pragma unroll
            for (int i = 0; i < 4; i++) acc[mt][nt][i] = 0.0f;

    // prologue fetch
    float4 ra[4], rb[4];
#pragma unroll
    for (int i = 0; i < 4; i++) {
        ra[i] = *(const float4*)(Aptr + i * 4);
        rb[i] = *(const float4*)(Bptr + i * 4);
    }

    for (int kt = 0; kt < K; kt += 32) {
        // store staged regs -> smem (cvt to tf32)
#pragma unroll
        for (int i = 0; i < 4; i++) {
            uint4 ua = make_uint4(f2tf32(ra[i].x), f2tf32(ra[i].y),
                                  f2tf32(ra[i].z), f2tf32(ra[i].w));
            *(uint4*)&As[arow][abase + i * 4] = ua;
            uint4 ub = make_uint4(f2tf32(rb[i].x), f2tf32(rb[i].y),
                                  f2tf32(rb[i].z), f2tf32(rb[i].w));
            *(uint4*)&Bs[brow][bcol + i * 4] = ub;
        }
        __syncthreads();

        // prefetch next tile
        if (kt + 32 < K) {
#pragma unroll
            for (int i = 0; i < 4; i++) {
                ra[i] = *(const float4*)(Aptr + kt + 32 + i * 4);
                rb[i] = *(const float4*)(Bptr + (size_t)(kt + 32) * N + i * 4);
            }
        }

        // compute 4 ksteps of 8
#pragma unroll
        for (int ks = 0; ks < 4; ks++) {
            const int k0 = ks * 8 + lk;
            unsigned af[4][4];
#pragma unroll
            for (int mt = 0; mt < 4; mt++) {
                const int row = wm + mt * 16 + lrow;
                af[mt][0] = As[row][k0];
                af[mt][1] = As[row + 8][k0];
                af[mt][2] = As[row][k0 + 4];
                af[mt][3] = As[row + 8][k0 + 4];
            }
#pragma unroll
            for (int nt = 0; nt < 4; nt++) {
                const int n0 = wn + nt * 8 + lrow;
                unsigned b0 = Bs[k0][n0];
                unsigned b1 = Bs[k0 + 4][n0];
#pragma unroll
                for (int mt = 0; mt < 4; mt++)
                    mma_tf32(acc[mt][nt], af[mt][0], af[mt][1], af[mt][2], af[mt][3], b0, b1);
            }
        }
        __syncthreads();
    }

    // epilogue
#pragma unroll
    for (int mt = 0; mt < 4; mt++) {
        const int row0 = bm + wm + mt * 16 + lrow;
#pragma unroll
        for (int nt = 0; nt < 4; nt++) {
            const int col = bn + wn + nt * 8 + lk * 2;
            float bx = 0.f, by = 0.f;
            if (bias) { bx = bias[col]; by = bias[col + 1]; }
            *(float2*)&C[(size_t)row0 * N + col] =
                make_float2(acc[mt][nt][0] + bx, acc[mt][nt][1] + by);
            *(float2*)&C[(size_t)(row0 + 8) * N + col] =
                make_float2(acc[mt][nt][2] + bx, acc[mt][nt][3] + by);
        }
    }
}

// ---------------------------------------------------------------------------
// RoPE + split + transpose: g_qkv[b,t,(s,h,d)] -> g_q/g_k/g_v [bh, t, d]
// q pre-scaled by 1/8.
// ---------------------------------------------------------------------------
__global__ void rope_split_kernel()
{
    const int idx = blockIdx.x * blockDim.x + threadIdx.x;
    const int d2 = idx & 31;
    const int t  = (idx >> 5) & (T_ - 1);
    const int bh = idx >> 16;
    const int h = bh & (H_ - 1);
    const int b = bh >> 4;

    const float* row = g_qkv + ((size_t)(b * T_ + t)) * (3 * D_) + h * DH_;
    const float q0 = row[d2];
    const float q1 = row[d2 + 32];
    const float k0 = row[D_ + d2];
    const float k1 = row[D_ + d2 + 32];
    const float v0 = row[2 * D_ + d2];
    const float v1 = row[2 * D_ + d2 + 32];

    const float inv = 1.0f / powf(10000.0f, (float)d2 * (1.0f / 32.0f));
    const float ang = (float)t * inv;
    float sn, cs;
    sincosf(ang, &sn, &cs);

    const size_t obase = ((size_t)bh * T_ + t) * DH_;
    g_q[obase + d2]      = (q0 * cs - q1 * sn) * 0.125f;
    g_q[obase + d2 + 32] = (q1 * cs + q0 * sn) * 0.125f;
    g_k[obase + d2]      = k0 * cs - k1 * sn;
    g_k[obase + d2 + 32] = k1 * cs + k0 * sn;
    g_v[obase + d2]      = v0;
    g_v[obase + d2 + 32] = v1;
}

// ---------------------------------------------------------------------------
// Tensor-core flash attention (tf32 mma, fp32 accum/softmax).
// Block = (64-row q tile, bh). 4 warps; warp w owns q rows w*16..w*16+15.
// smem (unsigned tf32): qs[64][68], ks[64][68], vs[64][72], ps[64][68].
// Fragment-read bank math: pad 68 -> bank 4*lrow+lk (distinct);
//                          pad 72 -> bank 8*lk+lrow (distinct).
// ---------------------------------------------------------------------------
#define QS_PAD 68
#define VS_PAD 72
#define ATTN_SMEM ((64 * QS_PAD * 3 + 64 * VS_PAD) * 4)

__global__ void __launch_bounds__(128)
attn_tc_kernel()
{
    extern __shared__ unsigned smu[];
    unsigned* qs = smu;                       // [64][68]
    unsigned* ks = qs + 64 * QS_PAD;          // [64][68]
    unsigned* ps = ks + 64 * QS_PAD;          // [64][68]
    unsigned* vs = ps + 64 * QS_PAD;          // [64][72]

    const int qt = blockIdx.x;
    const int bh = blockIdx.y;
    const int tid = threadIdx.x;
    const int lane = tid & 31;
    const int w = tid >> 5;
    const int lrow = lane >> 2;
    const int lk = lane & 3;
    const int wrow = w * 16;

    const float* Qb = g_q + ((size_t)bh * T_ + qt * 64) * DH_;
    const float* Kb = g_k + (size_t)bh * T_ * DH_;
    const float* Vb = g_v + (size_t)bh * T_ * DH_;

    // load Q tile -> tf32 smem. 64x64 = 1024 float4, 128 thr x 8 iters
#pragma unroll
    for (int i = 0; i < 8; i++) {
        const int e = tid + i * 128;
        const int r = e >> 4;
        const int c = (e & 15) << 2;
        float4 q4 = *(const float4*)&Qb[r * 64 + c];
        qs[r * QS_PAD + c + 0] = f2tf32(q4.x);
        qs[r * QS_PAD + c + 1] = f2tf32(q4.y);
        qs[r * QS_PAD + c + 2] = f2tf32(q4.z);
        qs[r * QS_PAD + c + 3] = f2tf32(q4.w);
    }

    float m0 = -1e30f, m1 = -1e30f, l0 = 0.f, l1 = 0.f;
    float oacc[8][4];
#pragma unroll
    for (int nt = 0; nt < 8; nt++)
#pragma unroll
        for (int i = 0; i < 4; i++) oacc[nt][i] = 0.f;

    for (int kt = 0; kt <= qt; kt++) {
        __syncthreads();   // prior PV readers of vs done; also covers qs on iter 0
#pragma unroll
        for (int i = 0; i < 8; i++) {
            const int e = tid + i * 128;
            const int r = e >> 4;
            const int c = (e & 15) << 2;
            float4 k4 = *(const float4*)(Kb + (size_t)(kt * 64 + r) * 64 + c);
            ks[r * QS_PAD + c + 0] = f2tf32(k4.x);
            ks[r * QS_PAD + c + 1] = f2tf32(k4.y);
            ks[r * QS_PAD + c + 2] = f2tf32(k4.z);
            ks[r * QS_PAD + c + 3] = f2tf32(k4.w);
            float4 v4 = *(const float4*)(Vb + (size_t)(kt * 64 + r) * 64 + c);
            vs[r * VS_PAD + c + 0] = f2tf32(v4.x);
            vs[r * VS_PAD + c + 1] = f2tf32(v4.y);
            vs[r * VS_PAD + c + 2] = f2tf32(v4.z);
            vs[r * VS_PAD + c + 3] = f2tf32(v4.w);
        }
        __syncthreads();

        // ---- S = Q @ K^T  (warp: 16 x 64) ----
        float sacc[8][4];
#pragma unroll
        for (int nt = 0; nt < 8; nt++)
#pragma unroll
            for (int i = 0; i < 4; i++) sacc[nt][i] = 0.f;

#pragma unroll
        for (int kc = 0; kc < 8; kc++) {
            const int k0 = kc * 8 + lk;
            const unsigned a0 = qs[(wrow + lrow) * QS_PAD + k0];
            const unsigned a1 = qs[(wrow + lrow + 8) * QS_PAD + k0];
            const unsigned a2 = qs[(wrow + lrow) * QS_PAD + k0 + 4];
            const unsigned a3 = qs[(wrow + lrow + 8) * QS_PAD + k0 + 4];
#pragma unroll
            for (int nt = 0; nt < 8; nt++) {
                const int n0 = nt * 8 + lrow;
                const unsigned b0 = ks[n0 * QS_PAD + k0];
                const unsigned b1 = ks[n0 * QS_PAD + k0 + 4];
                mma_tf32(sacc[nt], a0, a1, a2, a3, b0, b1);
            }
        }

        // ---- causal mask (diag tile) ----
        if (kt == qt) {
            const int r0 = wrow + lrow;
            const int r1 = r0 + 8;
#pragma unroll
            for (int nt = 0; nt < 8; nt++) {
                const int c0 = nt * 8 + lk * 2;
                if (c0 > r0)     sacc[nt][0] = -1e30f;
                if (c0 + 1 > r0) sacc[nt][1] = -1e30f;
                if (c0 > r1)     sacc[nt][2] = -1e30f;
                if (c0 + 1 > r1) sacc[nt][3] = -1e30f;
            }
        }

        // ---- online softmax on fragments ----
        float tm0 = -1e30f, tm1 = -1e30f;
#pragma unroll
        for (int nt = 0; nt < 8; nt++) {
            tm0 = fmaxf(tm0, fmaxf(sacc[nt][0], sacc[nt][1]));
            tm1 = fmaxf(tm1, fmaxf(sacc[nt][2], sacc[nt][3]));
        }
        tm0 = fmaxf(tm0, __shfl_xor_sync(0xffffffffu, tm0, 1));
        tm0 = fmaxf(tm0, __shfl_xor_sync(0xffffffffu, tm0, 2));
        tm1 = fmaxf(tm1, __shfl_xor_sync(0xffffffffu, tm1, 1));
        tm1 = fmaxf(tm1, __shfl_xor_sync(0xffffffffu, tm1, 2));

        const float mn0 = fmaxf(m0, tm0);
        const float mn1 = fmaxf(m1, tm1);
        const float corr0 = __expf(m0 - mn0);
        const float corr1 = __expf(m1 - mn1);
        m0 = mn0; m1 = mn1;

        float sum0 = 0.f, sum1 = 0.f;
        const int pr0 = (wrow + lrow) * QS_PAD;
        const int pr1 = (wrow + lrow + 8) * QS_PAD;
#pragma unroll
        for (int nt = 0; nt < 8; nt++) {
            const int c0 = nt * 8 + lk * 2;
            const float p00 = __expf(sacc[nt][0] - mn0);
            const float p01 = __expf(sacc[nt][1] - mn0);
            const float p10 = __expf(sacc[nt][2] - mn1);
            const float p11 = __expf(sacc[nt][3] - mn1);
            sum0 += p00 + p01;
            sum1 += p10 + p11;
            ps[pr0 + c0]     = f2tf32(p00);
            ps[pr0 + c0 + 1] = f2tf32(p01);
            ps[pr1 + c0]     = f2tf32(p10);
            ps[pr1 + c0 + 1] = f2tf32(p11);
        }
        sum0 += __shfl_xor_sync(0xffffffffu, sum0, 1);
        sum0 += __shfl_xor_sync(0xffffffffu, sum0, 2);
        sum1 += __shfl_xor_sync(0xffffffffu, sum1, 1);
        sum1 += __shfl_xor_sync(0xffffffffu, sum1, 2);
        l0 = l0 * corr0 + sum0;
        l1 = l1 * corr1 + sum1;

#pragma unroll
        for (int nt = 0; nt < 8; nt++) {
            oacc[nt][0] *= corr0;
            oacc[nt][1] *= corr0;
            oacc[nt][2] *= corr1;
            oacc[nt][3] *= corr1;
        }
        __syncwarp();

        // ---- O += P @ V  (warp: 16 x 64) ----
#pragma unroll
        for (int kc = 0; kc < 8; kc++) {
            const int k0 = kc * 8 + lk;
            const unsigned a0 = ps[pr0 + k0];
            const unsigned a1 = ps[pr1 + k0];
            const unsigned a2 = ps[pr0 + k0 + 4];
            const unsigned a3 = ps[pr1 + k0 + 4];
#pragma unroll
            for (int nt = 0; nt < 8; nt++) {
                const int n0 = nt * 8 + lrow;
                const unsigned b0 = vs[k0 * VS_PAD + n0];
                const unsigned b1 = vs[(k0 + 4) * VS_PAD + n0];
                mma_tf32(oacc[nt], a0, a1, a2, a3, b0, b1);
            }
        }
    }

    // ---- epilogue ----
    const int b = bh >> 4;
    const int h = bh & (H_ - 1);
    const float il0 = 1.0f / l0;
    const float il1 = 1.0f / l1;
    const int t0 = qt * 64 + wrow + lrow;
    const int t1 = t0 + 8;
    const size_t base0 = ((size_t)(b * T_ + t0)) * D_ + h * DH_;
    const size_t base1 = ((size_t)(b * T_ + t1)) * D_ + h * DH_;
#pragma unroll
    for (int nt = 0; nt < 8; nt++) {
        const int c0 = nt * 8 + lk * 2;
        *(float2*)&g_attn[base0 + c0] = make_float2(oacc[nt][0] * il0, oacc[nt][1] * il0);
        *(float2*)&g_attn[base1 + c0] = make_float2(oacc[nt][2] * il1, oacc[nt][3] * il1);
    }
}

// ---------------------------------------------------------------------------
// kernel_launch
// ---------------------------------------------------------------------------
extern "C" void kernel_launch(void* const* d_in, const int* in_sizes, int n_in,
                              void* d_out, int out_size)
{
    (void)in_sizes; (void)n_in; (void)out_size;
    const float* x     = (const float*)d_in[0];
    const float* qkv_w = (const float*)d_in[2];
    const float* out_w = (const float*)d_in[3];
    const float* out_b = (const float*)d_in[4];
    float* out = (float*)d_out;

    void* p_qkv;
    void* p_attn;
    cudaGetSymbolAddress(&p_qkv, g_qkv);
    cudaGetSymbolAddress(&p_attn, g_attn);

    cudaFuncSetAttribute(attn_tc_kernel,
                         cudaFuncAttributeMaxDynamicSharedMemorySize, ATTN_SMEM);

    // 1) QKV projection (tf32 tensor cores)
    gemm_tf32<<<dim3((3 * D_) / 128, NROW / 128), 256>>>(
        x, qkv_w, nullptr, (float*)p_qkv, NROW, 3 * D_, D_);

    // 2) RoPE + split/transpose
    rope_split_kernel<<<(BH_ * T_ * 32) / 256, 256>>>();

    // 3) causal flash attention (tensor cores)
    attn_tc_kernel<<<dim3(T_ / 64, BH_), 128, ATTN_SMEM>>>();

    // 4) output projection + bias (tf32 tensor cores)
    gemm_tf32<<<dim3(D_ / 128, NROW / 128), 256>>>(
        (const float*)p_attn, out_w, out_b, out, NROW, D_, D_);
}